// round 13
// baseline (speedup 1.0000x reference)
#include <cuda_runtime.h>
#include <cuda_bf16.h>

#define NPTS 2048
#define TPB  256
#define QPB  128                  // queries per block (2 threads per query)
#define TILES (NPTS / QPB)        // 16
#define KNN  16
#define NB   8
#define G    8
#define NGROUPS (NPTS / G)        // 256
#define HGROUPS (NGROUPS / 2)     // 128 groups per half-thread
#define STPB 1024
#define NBLOCKS (TILES * NB * 2)  // 256
#define NWIN (NPTS / 32)
#define NWARPS_S (STPB / 32)

__device__ float g_part[2 * NB * TILES];
__device__ float4 g_sorted[2 * NB * NPTS];
__device__ unsigned g_cnt;

#define CE(a, b) { float _lo = fminf(a, b); float _hi = fmaxf(a, b); a = _lo; b = _hi; }

#define MERGE_GROUP(c, best) {                                              \
    CE(c[0], c[1]); CE(c[2], c[3]); CE(c[4], c[5]); CE(c[6], c[7]);         \
    CE(c[0], c[2]); CE(c[1], c[3]); CE(c[4], c[6]); CE(c[5], c[7]);         \
    CE(c[1], c[2]); CE(c[5], c[6]);                                         \
    CE(c[0], c[4]); CE(c[1], c[5]); CE(c[2], c[6]); CE(c[3], c[7]);         \
    CE(c[2], c[4]); CE(c[3], c[5]);                                         \
    CE(c[1], c[2]); CE(c[3], c[4]); CE(c[5], c[6]);                         \
    best[15] = fminf(best[15], c[0]);                                       \
    best[14] = fminf(best[14], c[1]);                                       \
    best[13] = fminf(best[13], c[2]);                                       \
    best[12] = fminf(best[12], c[3]);                                       \
    best[11] = fminf(best[11], c[4]);                                       \
    best[10] = fminf(best[10], c[5]);                                       \
    best[9]  = fminf(best[9],  c[6]);                                       \
    best[8]  = fminf(best[8],  c[7]);                                       \
    _Pragma("unroll")                                                       \
    for (int t = 0; t < 8; t++)  CE(best[t], best[t + 8]);                  \
    _Pragma("unroll")                                                       \
    for (int hh = 0; hh < 16; hh += 8)                                      \
        for (int t = 0; t < 4; t++) CE(best[hh + t], best[hh + t + 4]);     \
    _Pragma("unroll")                                                       \
    for (int hh = 0; hh < 16; hh += 4)                                      \
        for (int t = 0; t < 2; t++) CE(best[hh + t], best[hh + t + 2]);     \
    _Pragma("unroll")                                                       \
    for (int hh = 0; hh < 16; hh += 2)                                      \
        CE(best[hh], best[hh + 1]);                                         \
}

#define DIST8(arr, base) {                                                  \
    _Pragma("unroll")                                                       \
    for (int u = 0; u < G; u++) {                                           \
        const float4 q = sm[(base) + u];                                    \
        arr[u] = fmaf(q.x, m2x, fmaf(q.y, m2y, fmaf(q.z, m2z, si + q.w)));  \
    }                                                                       \
}

#define MIN8(arr) fminf(fminf(fminf(arr[0], arr[1]), fminf(arr[2], arr[3])),\
                        fminf(fminf(arr[4], arr[5]), fminf(arr[6], arr[7])))

__device__ __forceinline__ unsigned expand3(unsigned v) {
    v &= 0x3FFu;
    v = (v | (v << 16)) & 0x030000FFu;
    v = (v | (v << 8))  & 0x0300F00Fu;
    v = (v | (v << 4))  & 0x030C30C3u;
    v = (v | (v << 2))  & 0x09249249u;
    return v;
}

__global__ void __launch_bounds__(STPB, 1)
sort_kernel(const float* __restrict__ seed, const float* __restrict__ gt)
{
    __shared__ unsigned keys[NPTS];
    __shared__ float4 spts[NPTS];

    const int b = blockIdx.x;
    const int z = blockIdx.y;
    const float* pts = (z == 0 ? seed : gt) + (size_t)b * NPTS * 3;
    const int tid  = threadIdx.x;
    const int warp = tid >> 5;
    const int lane = tid & 31;

#pragma unroll
    for (int j = tid; j < NPTS; j += STPB) {
        const float x  = pts[3 * j + 0];
        const float y  = pts[3 * j + 1];
        const float zc = pts[3 * j + 2];
        spts[j] = make_float4(x, y, zc, fmaf(x, x, fmaf(y, y, zc * zc)));
        const unsigned qx = (unsigned)fminf(fmaxf((x  + 4.0f) * 16.0f, 0.0f), 127.0f);
        const unsigned qy = (unsigned)fminf(fmaxf((y  + 4.0f) * 16.0f, 0.0f), 127.0f);
        const unsigned qz = (unsigned)fminf(fmaxf((zc + 4.0f) * 16.0f, 0.0f), 127.0f);
        const unsigned code = (expand3(qx) << 2) | (expand3(qy) << 1) | expand3(qz);
        keys[j] = (code << 11) | (unsigned)j;   // unique -> deterministic
    }
    __syncthreads();

    // k = 2..32 entirely in registers
#pragma unroll
    for (int w = warp; w < NWIN; w += NWARPS_S) {
        unsigned v = keys[w * 32 + lane];
#pragma unroll
        for (unsigned k = 2; k <= 16; k <<= 1) {
#pragma unroll
            for (unsigned j = k >> 1; j > 0; j >>= 1) {
                const unsigned o = __shfl_xor_sync(0xffffffffu, v, j);
                const bool up    = ((lane & k) == 0u);
                const bool lower = ((lane & j) == 0u);
                v = (lower == up) ? (v < o ? v : o) : (v > o ? v : o);
            }
        }
        {
            const bool up = ((w & 1) == 0);
#pragma unroll
            for (unsigned j = 16; j > 0; j >>= 1) {
                const unsigned o = __shfl_xor_sync(0xffffffffu, v, j);
                const bool lower = ((lane & j) == 0u);
                v = (lower == up) ? (v < o ? v : o) : (v > o ? v : o);
            }
        }
        keys[w * 32 + lane] = v;
    }
    __syncthreads();

    for (unsigned k = 64; k <= NPTS; k <<= 1) {
        for (unsigned jj = k >> 1; jj >= 32; jj >>= 1) {
            const unsigned t = (unsigned)tid;
            const unsigned i = ((t & ~(jj - 1u)) << 1) | (t & (jj - 1u));
            const unsigned pp = i | jj;
            const bool up = ((i & k) == 0u);
            const unsigned a  = keys[i];
            const unsigned c  = keys[pp];
            const unsigned lo = a < c ? a : c;
            const unsigned hi = a < c ? c : a;
            keys[i]  = up ? lo : hi;
            keys[pp] = up ? hi : lo;
            __syncthreads();
        }
#pragma unroll
        for (int w = warp; w < NWIN; w += NWARPS_S) {
            unsigned v = keys[w * 32 + lane];
            const bool up = (((unsigned)(w * 32) & k) == 0u);
#pragma unroll
            for (unsigned j = 16; j > 0; j >>= 1) {
                const unsigned o = __shfl_xor_sync(0xffffffffu, v, j);
                const bool lower = ((lane & j) == 0u);
                v = (lower == up) ? (v < o ? v : o) : (v > o ? v : o);
            }
            keys[w * 32 + lane] = v;
        }
        __syncthreads();
    }

    float4* dst = g_sorted + (size_t)(z * NB + b) * NPTS;
#pragma unroll
    for (int idx = tid; idx < NPTS; idx += STPB)
        dst[idx] = spts[keys[idx] & 2047u];
}

__global__ void __launch_bounds__(TPB, 2)
knn_kernel(float* __restrict__ out)
{
    __shared__ float4 sm[NPTS];           // 32 KB (reused as merge scratch)
    __shared__ float warp_sums[4];
    __shared__ unsigned s_ticket;

    const int tile = blockIdx.x;          // 0..15 (128 queries each)
    const int b    = blockIdx.y;
    const int z    = blockIdx.z;

    const float4* src = g_sorted + (size_t)(z * NB + b) * NPTS;
    for (int j = threadIdx.x; j < NPTS; j += TPB)
        sm[j] = src[j];
    __syncthreads();

    const int tid  = threadIdx.x;
    const int q    = tid & (QPB - 1);     // query within tile
    const int h    = tid >> 7;            // half: 0 = even groups, 1 = odd
    const int warp = tid >> 5;

    const int i = tile * QPB + q;
    const float4 p = sm[i];
    const float si  = p.w;
    const float m2x = -2.0f * p.x;
    const float m2y = -2.0f * p.y;
    const float m2z = -2.0f * p.z;

    float best[KNN];
#pragma unroll
    for (int t = 0; t < KNN; t++) best[t] = 3.4e38f;

    // own-blob rotation (uniform per warp); parity h selects half the groups
    const int g0 = tile * 16 + (warp & 3) * 4;

#pragma unroll 1
    for (int gg = 0; gg < HGROUPS; gg += 4) {
        const int gA = (((g0 + 2 * (gg + 0) + h) & (NGROUPS - 1)) << 3);
        const int gB = (((g0 + 2 * (gg + 1) + h) & (NGROUPS - 1)) << 3);
        const int gC = (((g0 + 2 * (gg + 2) + h) & (NGROUPS - 1)) << 3);
        const int gD = (((g0 + 2 * (gg + 3) + h) & (NGROUPS - 1)) << 3);

        float a[G], c[G], d[G], e[G];
        DIST8(a, gA);
        DIST8(c, gB);
        DIST8(d, gC);
        DIST8(e, gD);

        const float ma = MIN8(a);
        const float mb = MIN8(c);
        const float mc = MIN8(d);
        const float md = MIN8(e);

        const float thr = best[KNN - 1];
        const bool enterA = __any_sync(0xffffffffu, ma < thr);
        const bool enterB = __any_sync(0xffffffffu, mb < thr);
        const bool enterC = __any_sync(0xffffffffu, mc < thr);
        const bool enterD = __any_sync(0xffffffffu, md < thr);

        if (enterA) { MERGE_GROUP(a, best); }
        if (enterB) { MERGE_GROUP(c, best); }
        if (enterC) { MERGE_GROUP(d, best); }
        if (enterD) { MERGE_GROUP(e, best); }
    }

    // ---- merge the two halves per query: 16 smallest of A ∪ B via pairwise min
    __syncthreads();                       // done reading sm[] as points
    float* bs = (float*)sm;                // scratch: 256 * 17 floats (padded)
#pragma unroll
    for (int t = 0; t < KNN; t++)
        bs[tid * 17 + t] = best[t];
    __syncthreads();

    float s = 0.0f;
    if (h == 0) {
        const float* pb = bs + (tid + QPB) * 17;
#pragma unroll
        for (int t = 0; t < KNN; t++)
            s += fminf(best[t], pb[KNN - 1 - t]);   // exact 16-smallest multiset
        s *= (1.0f / KNN);

#pragma unroll
        for (int off = 16; off > 0; off >>= 1)
            s += __shfl_down_sync(0xffffffffu, s, off);
        if ((tid & 31) == 0) warp_sums[warp] = s;
    }
    __syncthreads();

    if (tid == 0) {
        const float acc = ((warp_sums[0] + warp_sums[1]) +
                           (warp_sums[2] + warp_sums[3]));
        g_part[(z * NB + b) * TILES + tile] = acc;
        __threadfence();
        s_ticket = atomicAdd(&g_cnt, 1u);
    }
    __syncthreads();

    if (s_ticket == NBLOCKS - 1) {
        const int lane = threadIdx.x;
        if (lane < 32) {
            float val = 0.0f;
            if (lane < NB) {
                float S = 0.0f, Gv = 0.0f;
#pragma unroll
                for (int t = 0; t < TILES; t++) {
                    S  += g_part[(0 * NB + lane) * TILES + t];
                    Gv += g_part[(1 * NB + lane) * TILES + t];
                }
                const float dd = (S - Gv) * (1.0f / (float)NPTS);
                val = dd * dd;
            }
#pragma unroll
            for (int off = 4; off > 0; off >>= 1)
                val += __shfl_down_sync(0xffffffffu, val, off);
            if (lane == 0) {
                out[0] = val * (1.0f / (float)NB);
                g_cnt = 0;   // self-reset for graph replay
            }
        }
    }
}

extern "C" void kernel_launch(void* const* d_in, const int* in_sizes, int n_in,
                              void* d_out, int out_size)
{
    const float* seed = (const float*)d_in[0];
    const float* gt_s = (const float*)d_in[1];
    float* out = (float*)d_out;

    dim3 sgrid(NB, 2);
    sort_kernel<<<sgrid, STPB>>>(seed, gt_s);

    dim3 grid(TILES, NB, 2);
    knn_kernel<<<grid, TPB>>>(out);
}

// round 16
// speedup vs baseline: 1.1600x; 1.1600x over previous
#include <cuda_runtime.h>
#include <cuda_bf16.h>

#define NPTS 2048
#define TPB  256
#define QPB  128                  // queries per block (2 threads per query)
#define TILES (NPTS / QPB)        // 16
#define KNN  16
#define NB   8
#define G    8
#define NGROUPS (NPTS / G)        // 256
#define HGROUPS (NGROUPS / 2)     // 128 groups per half-thread
#define STPB 1024
#define NBLOCKS (TILES * NB * 2)  // 256
#define NWIN (NPTS / 32)
#define NWARPS_S (STPB / 32)

__device__ float g_part[2 * NB * TILES];
__device__ float4 g_sorted[2 * NB * NPTS];
__device__ unsigned g_cnt;

#define CE(a, b) { float _lo = fminf(a, b); float _hi = fmaxf(a, b); a = _lo; b = _hi; }

#define MERGE_GROUP(c, best) {                                              \
    CE(c[0], c[1]); CE(c[2], c[3]); CE(c[4], c[5]); CE(c[6], c[7]);         \
    CE(c[0], c[2]); CE(c[1], c[3]); CE(c[4], c[6]); CE(c[5], c[7]);         \
    CE(c[1], c[2]); CE(c[5], c[6]);                                         \
    CE(c[0], c[4]); CE(c[1], c[5]); CE(c[2], c[6]); CE(c[3], c[7]);         \
    CE(c[2], c[4]); CE(c[3], c[5]);                                         \
    CE(c[1], c[2]); CE(c[3], c[4]); CE(c[5], c[6]);                         \
    best[15] = fminf(best[15], c[0]);                                       \
    best[14] = fminf(best[14], c[1]);                                       \
    best[13] = fminf(best[13], c[2]);                                       \
    best[12] = fminf(best[12], c[3]);                                       \
    best[11] = fminf(best[11], c[4]);                                       \
    best[10] = fminf(best[10], c[5]);                                       \
    best[9]  = fminf(best[9],  c[6]);                                       \
    best[8]  = fminf(best[8],  c[7]);                                       \
    _Pragma("unroll")                                                       \
    for (int t = 0; t < 8; t++)  CE(best[t], best[t + 8]);                  \
    _Pragma("unroll")                                                       \
    for (int hh = 0; hh < 16; hh += 8)                                      \
        for (int t = 0; t < 4; t++) CE(best[hh + t], best[hh + t + 4]);     \
    _Pragma("unroll")                                                       \
    for (int hh = 0; hh < 16; hh += 4)                                      \
        for (int t = 0; t < 2; t++) CE(best[hh + t], best[hh + t + 2]);     \
    _Pragma("unroll")                                                       \
    for (int hh = 0; hh < 16; hh += 2)                                      \
        CE(best[hh], best[hh + 1]);                                         \
}

#define DIST8(arr, base) {                                                  \
    _Pragma("unroll")                                                       \
    for (int u = 0; u < G; u++) {                                           \
        const float4 q = sm[(base) + u];                                    \
        arr[u] = fmaf(q.x, m2x, fmaf(q.y, m2y, fmaf(q.z, m2z, si + q.w)));  \
    }                                                                       \
}

#define MIN8(arr) fminf(fminf(fminf(arr[0], arr[1]), fminf(arr[2], arr[3])),\
                        fminf(fminf(arr[4], arr[5]), fminf(arr[6], arr[7])))

__device__ __forceinline__ unsigned expand3(unsigned v) {
    v &= 0x3FFu;
    v = (v | (v << 16)) & 0x030000FFu;
    v = (v | (v << 8))  & 0x0300F00Fu;
    v = (v | (v << 4))  & 0x030C30C3u;
    v = (v | (v << 2))  & 0x09249249u;
    return v;
}

__global__ void __launch_bounds__(STPB, 1)
sort_kernel(const float* __restrict__ seed, const float* __restrict__ gt)
{
    __shared__ unsigned keys[NPTS];
    __shared__ float4 spts[NPTS];

    const int b = blockIdx.x;
    const int z = blockIdx.y;
    const float* pts = (z == 0 ? seed : gt) + (size_t)b * NPTS * 3;
    const int tid  = threadIdx.x;
    const int warp = tid >> 5;
    const int lane = tid & 31;

#pragma unroll
    for (int j = tid; j < NPTS; j += STPB) {
        const float x  = pts[3 * j + 0];
        const float y  = pts[3 * j + 1];
        const float zc = pts[3 * j + 2];
        spts[j] = make_float4(x, y, zc, fmaf(x, x, fmaf(y, y, zc * zc)));
        const unsigned qx = (unsigned)fminf(fmaxf((x  + 4.0f) * 16.0f, 0.0f), 127.0f);
        const unsigned qy = (unsigned)fminf(fmaxf((y  + 4.0f) * 16.0f, 0.0f), 127.0f);
        const unsigned qz = (unsigned)fminf(fmaxf((zc + 4.0f) * 16.0f, 0.0f), 127.0f);
        const unsigned code = (expand3(qx) << 2) | (expand3(qy) << 1) | expand3(qz);
        keys[j] = (code << 11) | (unsigned)j;   // unique -> deterministic
    }
    __syncthreads();

    // k = 2..32 entirely in registers
#pragma unroll
    for (int w = warp; w < NWIN; w += NWARPS_S) {
        unsigned v = keys[w * 32 + lane];
#pragma unroll
        for (unsigned k = 2; k <= 16; k <<= 1) {
#pragma unroll
            for (unsigned j = k >> 1; j > 0; j >>= 1) {
                const unsigned o = __shfl_xor_sync(0xffffffffu, v, j);
                const bool up    = ((lane & k) == 0u);
                const bool lower = ((lane & j) == 0u);
                v = (lower == up) ? (v < o ? v : o) : (v > o ? v : o);
            }
        }
        {
            const bool up = ((w & 1) == 0);
#pragma unroll
            for (unsigned j = 16; j > 0; j >>= 1) {
                const unsigned o = __shfl_xor_sync(0xffffffffu, v, j);
                const bool lower = ((lane & j) == 0u);
                v = (lower == up) ? (v < o ? v : o) : (v > o ? v : o);
            }
        }
        keys[w * 32 + lane] = v;
    }
    __syncthreads();

    for (unsigned k = 64; k <= NPTS; k <<= 1) {
        for (unsigned jj = k >> 1; jj >= 32; jj >>= 1) {
            const unsigned t = (unsigned)tid;
            const unsigned i = ((t & ~(jj - 1u)) << 1) | (t & (jj - 1u));
            const unsigned pp = i | jj;
            const bool up = ((i & k) == 0u);
            const unsigned a  = keys[i];
            const unsigned c  = keys[pp];
            const unsigned lo = a < c ? a : c;
            const unsigned hi = a < c ? c : a;
            keys[i]  = up ? lo : hi;
            keys[pp] = up ? hi : lo;
            __syncthreads();
        }
#pragma unroll
        for (int w = warp; w < NWIN; w += NWARPS_S) {
            unsigned v = keys[w * 32 + lane];
            const bool up = (((unsigned)(w * 32) & k) == 0u);
#pragma unroll
            for (unsigned j = 16; j > 0; j >>= 1) {
                const unsigned o = __shfl_xor_sync(0xffffffffu, v, j);
                const bool lower = ((lane & j) == 0u);
                v = (lower == up) ? (v < o ? v : o) : (v > o ? v : o);
            }
            keys[w * 32 + lane] = v;
        }
        __syncthreads();
    }

    float4* dst = g_sorted + (size_t)(z * NB + b) * NPTS;
#pragma unroll
    for (int idx = tid; idx < NPTS; idx += STPB)
        dst[idx] = spts[keys[idx] & 2047u];
}

__global__ void __launch_bounds__(TPB, 2)
knn_kernel(float* __restrict__ out)
{
    __shared__ float4 sm[NPTS];           // 32 KB
    __shared__ float warp_sums[TPB / 32];
    __shared__ unsigned s_ticket;

    const int tile = blockIdx.x;          // 0..15 (128 queries each)
    const int b    = blockIdx.y;
    const int z    = blockIdx.z;

    const float4* src = g_sorted + (size_t)(z * NB + b) * NPTS;
    for (int j = threadIdx.x; j < NPTS; j += TPB)
        sm[j] = src[j];
    __syncthreads();

    const int tid  = threadIdx.x;
    const int lane = tid & 31;
    const int warp = tid >> 5;
    const int h    = lane >> 4;           // half: lanes 0-15 even groups, 16-31 odd
    const int q    = warp * 16 + (lane & 15);   // query within tile (16 per warp)

    const int i = tile * QPB + q;
    const float4 p = sm[i];
    const float si  = p.w;
    const float m2x = -2.0f * p.x;
    const float m2y = -2.0f * p.y;
    const float m2z = -2.0f * p.z;

    float best[KNN];
#pragma unroll
    for (int t = 0; t < KNN; t++) best[t] = 3.4e38f;

    // warp's 16 queries span 2 groups; rotate scan to start at own blob
    const int g0 = tile * 16 + warp * 2;

#pragma unroll 1
    for (int gg = 0; gg < HGROUPS; gg += 4) {
        const int gA = (((g0 + 2 * (gg + 0) + h) & (NGROUPS - 1)) << 3);
        const int gB = (((g0 + 2 * (gg + 1) + h) & (NGROUPS - 1)) << 3);
        const int gC = (((g0 + 2 * (gg + 2) + h) & (NGROUPS - 1)) << 3);
        const int gD = (((g0 + 2 * (gg + 3) + h) & (NGROUPS - 1)) << 3);

        float a[G], c[G], d[G], e[G];
        DIST8(a, gA);
        DIST8(c, gB);
        DIST8(d, gC);
        DIST8(e, gD);

        const float ma = MIN8(a);
        const float mb = MIN8(c);
        const float mc = MIN8(d);
        const float md = MIN8(e);

        // Joint threshold: 16th of the union is <= min of the halves' 16ths.
        // Skipping d >= thr can never drop a member of the final joint top-16.
        const float myw = best[KNN - 1];
        const float thr = fminf(myw, __shfl_xor_sync(0xffffffffu, myw, 16));

        const bool enterA = __any_sync(0xffffffffu, ma < thr);
        const bool enterB = __any_sync(0xffffffffu, mb < thr);
        const bool enterC = __any_sync(0xffffffffu, mc < thr);
        const bool enterD = __any_sync(0xffffffffu, md < thr);

        if (enterA) { MERGE_GROUP(a, best); }
        if (enterB) { MERGE_GROUP(c, best); }
        if (enterC) { MERGE_GROUP(d, best); }
        if (enterD) { MERGE_GROUP(e, best); }
    }

    // Joint top-16 sum via pairwise-min across the lane pair (pure shuffles).
    // Both lanes of a pair compute the identical sum (multiset symmetry).
    float s = 0.0f;
#pragma unroll
    for (int t = 0; t < KNN; t++) {
        const float ot = __shfl_xor_sync(0xffffffffu, best[KNN - 1 - t], 16);
        s += fminf(best[t], ot);
    }
    s *= (1.0f / KNN);

    // Each query's sum appears in 2 lanes -> halve after full-warp reduction
#pragma unroll
    for (int off = 16; off > 0; off >>= 1)
        s += __shfl_down_sync(0xffffffffu, s, off);

    if (lane == 0) warp_sums[warp] = s * 0.5f;
    __syncthreads();

    if (tid == 0) {
        float acc = 0.0f;
#pragma unroll
        for (int w = 0; w < TPB / 32; w++) acc += warp_sums[w];
        g_part[(z * NB + b) * TILES + tile] = acc;
        __threadfence();
        s_ticket = atomicAdd(&g_cnt, 1u);
    }
    __syncthreads();

    if (s_ticket == NBLOCKS - 1) {
        if (tid < 32) {
            float val = 0.0f;
            if (tid < NB) {
                float S = 0.0f, Gv = 0.0f;
#pragma unroll
                for (int t = 0; t < TILES; t++) {
                    S  += g_part[(0 * NB + tid) * TILES + t];
                    Gv += g_part[(1 * NB + tid) * TILES + t];
                }
                const float dd = (S - Gv) * (1.0f / (float)NPTS);
                val = dd * dd;
            }
#pragma unroll
            for (int off = 4; off > 0; off >>= 1)
                val += __shfl_down_sync(0xffffffffu, val, off);
            if (tid == 0) {
                out[0] = val * (1.0f / (float)NB);
                g_cnt = 0;   // self-reset for graph replay
            }
        }
    }
}

extern "C" void kernel_launch(void* const* d_in, const int* in_sizes, int n_in,
                              void* d_out, int out_size)
{
    const float* seed = (const float*)d_in[0];
    const float* gt_s = (const float*)d_in[1];
    float* out = (float*)d_out;

    dim3 sgrid(NB, 2);
    sort_kernel<<<sgrid, STPB>>>(seed, gt_s);

    dim3 grid(TILES, NB, 2);
    knn_kernel<<<grid, TPB>>>(out);
}